// round 2
// baseline (speedup 1.0000x reference)
#include <cuda_runtime.h>
#include <math.h>
#include <stdint.h>

#define BB 32
#define NN 4096

// ---------------- static device scratch (no allocations allowed) ----------------
__device__ float4 g_pts1[BB*NN];
__device__ float4 g_pts2[BB*512];
__device__ int    g_fidx1[BB*512];
__device__ float  g_nxyz1[BB*512*3];
__device__ int    g_idx1[BB*512*32];
__device__ int    g_fidx2[BB*128];
__device__ float  g_nxyz2[BB*128*3];
__device__ int    g_idx2[BB*128*64];
__device__ float  g_feat1[BB*512*128];
__device__ float  g_feat2[BB*128*256];
__device__ float  g_feat3[BB*1024];
__device__ float  g_fc1o[BB*512];
__device__ float  g_fc2o[BB*256];
__device__ float  g_logits[BB*64];
__device__ float  g_bufA[67108864];   // 256 MiB ping
__device__ float  g_bufB[67108864];   // 256 MiB pong

// no-FMA fp32 helpers (must match XLA's elementwise mul/add ordering)
__device__ __forceinline__ float fm(float a, float b){ return __fmul_rn(a,b); }
__device__ __forceinline__ float fa(float a, float b){ return __fadd_rn(a,b); }

__device__ __forceinline__ uint32_t f2tf32(float x){
    uint32_t r;
    asm("cvt.rna.tf32.f32 %0, %1;" : "=r"(r) : "f"(x));
    return r;
}

#define MMA_TF32(c, a0,a1,a2,a3, b0,b1) \
  asm volatile("mma.sync.aligned.m16n8k8.row.col.f32.tf32.tf32.f32 " \
    "{%0,%1,%2,%3}, {%4,%5,%6,%7}, {%8,%9}, {%0,%1,%2,%3};" \
    : "+f"((c)[0]),"+f"((c)[1]),"+f"((c)[2]),"+f"((c)[3]) \
    : "r"(a0),"r"(a1),"r"(a2),"r"(a3),"r"(b0),"r"(b1))

// ---------------- pack xyz + sumsq into float4 for ball query ----------------
__global__ void prep_pts_kernel(const float* __restrict__ xyz, float4* __restrict__ pts, int total){
    int i = blockIdx.x*blockDim.x + threadIdx.x;
    if (i >= total) return;
    float x = xyz[i*3+0], y = xyz[i*3+1], z = xyz[i*3+2];
    pts[i] = make_float4(x, y, z, fa(fa(fm(x,x), fm(y,y)), fm(z,z)));
}

// ---------------- farthest point sampling: one block per batch ----------------
template<int PPT>
__global__ void fps_kernel(const float* __restrict__ xyz, int n, int m,
                           int* __restrict__ fidx, float* __restrict__ nxyz){
    const int T = 512;
    int b = blockIdx.x, tid = threadIdx.x;
    const float* p = xyz + (size_t)b*n*3;
    float px[PPT], py[PPT], pz[PPT], mind[PPT];
    #pragma unroll
    for (int i=0;i<PPT;i++){
        int j = tid + i*T;
        if (j < n){ px[i]=p[j*3]; py[i]=p[j*3+1]; pz[i]=p[j*3+2]; mind[i]=1e10f; }
        else mind[i] = -1e30f;
    }
    __shared__ float sv[16];
    __shared__ int   si[16];
    __shared__ float cur[3];
    __shared__ int   slast;
    int last = 0;
    for (int t=0;t<m;t++){
        if (tid == 0){
            fidx[b*m+t] = last;
            float cx=p[last*3], cy=p[last*3+1], cz=p[last*3+2];
            cur[0]=cx; cur[1]=cy; cur[2]=cz;
            nxyz[((size_t)b*m+t)*3+0]=cx;
            nxyz[((size_t)b*m+t)*3+1]=cy;
            nxyz[((size_t)b*m+t)*3+2]=cz;
        }
        __syncthreads();
        float cx=cur[0], cy=cur[1], cz=cur[2];
        float bv=-1e30f; int bj=0x7fffffff;
        #pragma unroll
        for (int i=0;i<PPT;i++){
            int j = tid + i*T;
            if (j < n){
                float dx=px[i]-cx, dy=py[i]-cy, dz=pz[i]-cz;
                float d = fa(fa(fm(dx,dx), fm(dy,dy)), fm(dz,dz));
                float mn = fminf(mind[i], d);
                mind[i] = mn;
                if (mn > bv){ bv=mn; bj=j; }
            }
        }
        #pragma unroll
        for (int off=16; off; off>>=1){
            float ov = __shfl_down_sync(0xffffffffu, bv, off);
            int   oj = __shfl_down_sync(0xffffffffu, bj, off);
            if (ov > bv || (ov == bv && oj < bj)){ bv=ov; bj=oj; }
        }
        if ((tid&31)==0){ sv[tid>>5]=bv; si[tid>>5]=bj; }
        __syncthreads();
        if (tid < 32){
            float v = (tid<16)? sv[tid] : -1e30f;
            int   j = (tid<16)? si[tid] : 0x7fffffff;
            #pragma unroll
            for (int off=16; off; off>>=1){
                float ov = __shfl_down_sync(0xffffffffu, v, off);
                int   oj = __shfl_down_sync(0xffffffffu, j, off);
                if (ov > v || (ov == v && oj < j)){ v=ov; j=oj; }
            }
            if (tid==0) slast = j;
        }
        __syncthreads();
        last = slast;
    }
}

// ---------------- ball query: one warp per centroid ----------------
template<int KS>
__global__ void ball_kernel(const float4* __restrict__ pts, const float* __restrict__ nxyz,
                            int n, int S, float r2, int* __restrict__ out){
    __shared__ int widx[8][KS];
    int w = threadIdx.x >> 5, lane = threadIdx.x & 31;
    int sg = blockIdx.x*8 + w;
    int b = sg / S;
    const float4* P = pts + (size_t)b*n;
    float cx = nxyz[(size_t)sg*3+0], cy = nxyz[(size_t)sg*3+1], cz = nxyz[(size_t)sg*3+2];
    float sn = fa(fa(fm(cx,cx), fm(cy,cy)), fm(cz,cz));
    int cnt = 0;
    for (int j0=0; j0<n && cnt<KS; j0+=32){
        int j = j0 + lane;
        float4 q = P[j];
        float dot = fa(fa(fm(cx,q.x), fm(cy,q.y)), fm(cz,q.z));
        float sqd = __fsub_rn(fa(sn, q.w), fm(2.0f, dot));
        bool inb = (sqd <= r2);
        unsigned msk = __ballot_sync(0xffffffffu, inb);
        int pos = cnt + __popc(msk & ((1u<<lane)-1u));
        if (inb && pos < KS) widx[w][pos] = j;
        cnt += __popc(msk);
    }
    __syncwarp();
    int c = cnt < KS ? cnt : KS;
    int first = widx[w][0];
    for (int p = c + lane; p < KS; p += 32) widx[w][p] = first;
    __syncwarp();
    for (int p = lane; p < KS; p += 32) out[(size_t)sg*KS + p] = widx[w][p];
}

// ---------------- group builders ----------------
__global__ void build_g1_kernel(const float* __restrict__ x, const float* __restrict__ nxyz,
                                const int* __restrict__ idx, float* __restrict__ g){
    int r = blockIdx.x*blockDim.x + threadIdx.x;
    if (r >= BB*512*32) return;
    int s = (r>>5) & 511, b = r >> 14;
    int j = idx[r];
    const float* pp = x    + ((size_t)b*NN  + j)*3;
    const float* cc = nxyz + ((size_t)b*512 + s)*3;
    g[(size_t)r*3+0] = pp[0]-cc[0];
    g[(size_t)r*3+1] = pp[1]-cc[1];
    g[(size_t)r*3+2] = pp[2]-cc[2];
}

__global__ void build_g2_kernel(const float* __restrict__ xyz1, const float* __restrict__ feat1,
                                const float* __restrict__ nxyz2, const int* __restrict__ idx,
                                float* __restrict__ g){
    long long e = (long long)blockIdx.x*blockDim.x + threadIdx.x;
    const long long total = (long long)262144*131;
    if (e >= total) return;
    int c = (int)(e % 131);
    int r = (int)(e / 131);
    int s = (r>>6) & 127, b = r >> 13;
    int j = idx[r];
    float v;
    if (c < 3) v = xyz1[((size_t)b*512 + j)*3 + c] - nxyz2[((size_t)b*128 + s)*3 + c];
    else       v = feat1[((size_t)b*512 + j)*128 + (c-3)];
    g[e] = v;
}

__global__ void build_g3_kernel(const float* __restrict__ nxyz2, const float* __restrict__ feat2,
                                float* __restrict__ g){
    int e = blockIdx.x*blockDim.x + threadIdx.x;
    if (e >= 4096*259) return;
    int c = e % 259, r = e / 259;
    float v = (c<3) ? nxyz2[(size_t)r*3+c] : feat2[(size_t)r*256 + (c-3)];
    g[e] = v;
}

// ---------------- max pool over group dim ----------------
__global__ void maxpool_kernel(const float* __restrict__ in, float* __restrict__ out,
                               int G, int Kp, int C){
    int e = blockIdx.x*blockDim.x + threadIdx.x;
    if (e >= G*C) return;
    int g = e / C, c = e % C;
    const float* p = in + (size_t)g*Kp*C + c;
    float v = p[0];
    for (int k=1;k<Kp;k++) v = fmaxf(v, p[(size_t)k*C]);
    out[(size_t)g*C + c] = v;
}

// ---------------- tensor-core GEMM (3xTF32 split, fp32-accurate) ----------------
// C[M,N] = relu?(A[M,K] @ W[N,K]^T + bias)
// Block tile: 128 x BN, BK=32. 8 warps: 2(m) x 4(n), warp tile 64 x (BN/4).
// smem layout per element (row,k): off = row*32 + (k ^ ((row&7)<<2))  (conflict-free
// for both STS.128 fill and all mma fragment LDS patterns).
template<int BN>
__global__ void __launch_bounds__(256)
tgemm_kernel(const float* __restrict__ A, const float* __restrict__ W,
             const float* __restrict__ bias, float* __restrict__ C,
             long long M, int N, int K, int doRelu)
{
    constexpr int NI = BN/32;     // 8-wide n-tiles per warp
    constexpr int WN = BN/4;      // warp n extent
    extern __shared__ float smem[];
    float* Ahi = smem;                  // 128*32
    float* Alo = Ahi + 128*32;
    float* Bhi = Alo + 128*32;          // BN*32
    float* Blo = Bhi + BN*32;

    int tid  = threadIdx.x;
    int lane = tid & 31, wid = tid >> 5;
    int wm = (wid & 1)*64;
    int wn = (wid >> 1)*WN;
    int gID = lane >> 2, tig = lane & 3;

    long long bm = (long long)blockIdx.y * 128;
    int bn = blockIdx.x * BN;

    float acc[4][NI][4];
    #pragma unroll
    for (int mi=0;mi<4;mi++)
        #pragma unroll
        for (int ni=0;ni<NI;ni++)
            #pragma unroll
            for (int r=0;r<4;r++) acc[mi][ni][r] = 0.f;

    int lm  = tid >> 3;       // 0..31
    int lkg = tid & 7;        // k-group of 4

    for (int k0 = 0; k0 < K; k0 += 32) {
        // ---- fill A tile (128x32), split hi/lo ----
        #pragma unroll
        for (int p=0;p<4;p++){
            int m = lm + p*32;
            long long gm = bm + m;
            float v[4];
            #pragma unroll
            for (int i=0;i<4;i++){
                int gk = k0 + lkg*4 + i;
                v[i] = (gm < M && gk < K) ? A[gm*(long long)K + gk] : 0.f;
            }
            uint32_t h[4], l[4];
            #pragma unroll
            for (int i=0;i<4;i++){
                h[i] = f2tf32(v[i]);
                l[i] = f2tf32(v[i] - __uint_as_float(h[i]));
            }
            int off = m*32 + ((lkg*4) ^ ((m&7)<<2));
            *reinterpret_cast<uint4*>(Ahi+off) = make_uint4(h[0],h[1],h[2],h[3]);
            *reinterpret_cast<uint4*>(Alo+off) = make_uint4(l[0],l[1],l[2],l[3]);
        }
        // ---- fill B tile (BNx32), split hi/lo ----
        #pragma unroll
        for (int p=0;p<BN/32;p++){
            int n = lm + p*32;
            int gn = bn + n;
            float v[4];
            #pragma unroll
            for (int i=0;i<4;i++){
                int gk = k0 + lkg*4 + i;
                v[i] = (gn < N && gk < K) ? W[(size_t)gn*K + gk] : 0.f;
            }
            uint32_t h[4], l[4];
            #pragma unroll
            for (int i=0;i<4;i++){
                h[i] = f2tf32(v[i]);
                l[i] = f2tf32(v[i] - __uint_as_float(h[i]));
            }
            int off = n*32 + ((lkg*4) ^ ((n&7)<<2));
            *reinterpret_cast<uint4*>(Bhi+off) = make_uint4(h[0],h[1],h[2],h[3]);
            *reinterpret_cast<uint4*>(Blo+off) = make_uint4(l[0],l[1],l[2],l[3]);
        }
        __syncthreads();

        #pragma unroll
        for (int kk=0; kk<4; kk++){
            int k8 = kk*8;
            int kA = k8 + tig;
            uint32_t ah[4][4], al[4][4];
            #pragma unroll
            for (int mi=0;mi<4;mi++){
                int m0 = wm + mi*16 + gID;
                int m1 = m0 + 8;
                int s0 = (m0&7)<<2, s1 = (m1&7)<<2;
                int o00 = m0*32 + (kA ^ s0);
                int o10 = m1*32 + (kA ^ s1);
                int o01 = m0*32 + ((kA+4) ^ s0);
                int o11 = m1*32 + ((kA+4) ^ s1);
                ah[mi][0]=__float_as_uint(Ahi[o00]); ah[mi][1]=__float_as_uint(Ahi[o10]);
                ah[mi][2]=__float_as_uint(Ahi[o01]); ah[mi][3]=__float_as_uint(Ahi[o11]);
                al[mi][0]=__float_as_uint(Alo[o00]); al[mi][1]=__float_as_uint(Alo[o10]);
                al[mi][2]=__float_as_uint(Alo[o01]); al[mi][3]=__float_as_uint(Alo[o11]);
            }
            #pragma unroll
            for (int ni=0; ni<NI; ni++){
                int n0 = wn + ni*8 + gID;
                int sb = (n0&7)<<2;
                int ob0 = n0*32 + (kA ^ sb);
                int ob1 = n0*32 + ((kA+4) ^ sb);
                uint32_t bh0=__float_as_uint(Bhi[ob0]), bh1=__float_as_uint(Bhi[ob1]);
                uint32_t bl0=__float_as_uint(Blo[ob0]), bl1=__float_as_uint(Blo[ob1]);
                #pragma unroll
                for (int mi=0;mi<4;mi++){
                    MMA_TF32(acc[mi][ni], ah[mi][0],ah[mi][1],ah[mi][2],ah[mi][3], bh0,bh1);
                    MMA_TF32(acc[mi][ni], ah[mi][0],ah[mi][1],ah[mi][2],ah[mi][3], bl0,bl1);
                    MMA_TF32(acc[mi][ni], al[mi][0],al[mi][1],al[mi][2],al[mi][3], bh0,bh1);
                }
            }
        }
        __syncthreads();
    }

    // ---- epilogue: bias + optional relu, float2 stores ----
    #pragma unroll
    for (int mi=0;mi<4;mi++){
        long long gm0 = bm + wm + mi*16 + gID;
        long long gm1 = gm0 + 8;
        #pragma unroll
        for (int ni=0;ni<NI;ni++){
            int gn = bn + wn + ni*8 + tig*2;
            if (gn >= N) continue;
            float bv0 = bias[gn];
            float bv1 = (gn+1 < N) ? bias[gn+1] : 0.f;
            float v0 = acc[mi][ni][0] + bv0;
            float v1 = acc[mi][ni][1] + bv1;
            float v2 = acc[mi][ni][2] + bv0;
            float v3 = acc[mi][ni][3] + bv1;
            if (doRelu){
                v0 = fmaxf(v0,0.f); v1 = fmaxf(v1,0.f);
                v2 = fmaxf(v2,0.f); v3 = fmaxf(v3,0.f);
            }
            if (gn+1 < N){
                if (gm0 < M) *reinterpret_cast<float2*>(&C[gm0*N + gn]) = make_float2(v0,v1);
                if (gm1 < M) *reinterpret_cast<float2*>(&C[gm1*N + gn]) = make_float2(v2,v3);
            } else {
                if (gm0 < M) C[gm0*N + gn] = v0;
                if (gm1 < M) C[gm1*N + gn] = v2;
            }
        }
    }
}

// ---------------- softmax over 40 classes, 32 rows ----------------
__global__ void softmax_kernel(const float* __restrict__ in, float* __restrict__ out){
    int b = threadIdx.y;
    int lane = threadIdx.x;
    float v0 = in[b*40 + lane];
    float v1 = (lane < 8) ? in[b*40 + lane + 32] : -INFINITY;
    float mx = fmaxf(v0, v1);
    #pragma unroll
    for (int off=16; off; off>>=1) mx = fmaxf(mx, __shfl_xor_sync(0xffffffffu, mx, off));
    float e0 = expf(v0 - mx);
    float e1 = (lane < 8) ? expf(v1 - mx) : 0.f;
    float sm = e0 + e1;
    #pragma unroll
    for (int off=16; off; off>>=1) sm += __shfl_xor_sync(0xffffffffu, sm, off);
    out[b*40 + lane] = e0 / sm;
    if (lane < 8) out[b*40 + lane + 32] = e1 / sm;
}

// ---------------- host launcher ----------------
static void tgemm(const float* A, const float* W, const float* bias, float* C,
                  long long M, int N, int K, int doRelu)
{
    int gy = (int)((M + 127)/128);
    if (N > 64){
        int smem = (128*32*2 + 128*32*2)*4;   // 64KB
        cudaFuncSetAttribute(tgemm_kernel<128>, cudaFuncAttributeMaxDynamicSharedMemorySize, smem);
        dim3 grid((N+127)/128, gy);
        tgemm_kernel<128><<<grid, 256, smem>>>(A, W, bias, C, M, N, K, doRelu);
    } else {
        int smem = (128*32*2 + 64*32*2)*4;    // 48KB
        cudaFuncSetAttribute(tgemm_kernel<64>, cudaFuncAttributeMaxDynamicSharedMemorySize, smem);
        dim3 grid((N+63)/64, gy);
        tgemm_kernel<64><<<grid, 256, smem>>>(A, W, bias, C, M, N, K, doRelu);
    }
}

extern "C" void kernel_launch(void* const* d_in, const int* in_sizes, int n_in,
                              void* d_out, int out_size)
{
    (void)in_sizes; (void)n_in; (void)out_size;
    const float* x    = (const float*)d_in[0];
    const float* w1[3]= {(const float*)d_in[1],(const float*)d_in[3],(const float*)d_in[5]};
    const float* b1[3]= {(const float*)d_in[2],(const float*)d_in[4],(const float*)d_in[6]};
    const float* w2[3]= {(const float*)d_in[7],(const float*)d_in[9],(const float*)d_in[11]};
    const float* b2[3]= {(const float*)d_in[8],(const float*)d_in[10],(const float*)d_in[12]};
    const float* w3[3]= {(const float*)d_in[13],(const float*)d_in[15],(const float*)d_in[17]};
    const float* b3[3]= {(const float*)d_in[14],(const float*)d_in[16],(const float*)d_in[18]};
    const float* fc1w=(const float*)d_in[19]; const float* fc1b=(const float*)d_in[20];
    const float* fc2w=(const float*)d_in[21]; const float* fc2b=(const float*)d_in[22];
    const float* fc3w=(const float*)d_in[23]; const float* fc3b=(const float*)d_in[24];

    float4 *pts1, *pts2;
    int *fidx1, *fidx2, *idx1, *idx2;
    float *nxyz1, *nxyz2, *feat1, *feat2, *feat3, *fc1o, *fc2o, *logits, *bufA, *bufB;
    cudaGetSymbolAddress((void**)&pts1,  g_pts1);
    cudaGetSymbolAddress((void**)&pts2,  g_pts2);
    cudaGetSymbolAddress((void**)&fidx1, g_fidx1);
    cudaGetSymbolAddress((void**)&nxyz1, g_nxyz1);
    cudaGetSymbolAddress((void**)&idx1,  g_idx1);
    cudaGetSymbolAddress((void**)&fidx2, g_fidx2);
    cudaGetSymbolAddress((void**)&nxyz2, g_nxyz2);
    cudaGetSymbolAddress((void**)&idx2,  g_idx2);
    cudaGetSymbolAddress((void**)&feat1, g_feat1);
    cudaGetSymbolAddress((void**)&feat2, g_feat2);
    cudaGetSymbolAddress((void**)&feat3, g_feat3);
    cudaGetSymbolAddress((void**)&fc1o,  g_fc1o);
    cudaGetSymbolAddress((void**)&fc2o,  g_fc2o);
    cudaGetSymbolAddress((void**)&logits,g_logits);
    cudaGetSymbolAddress((void**)&bufA,  g_bufA);
    cudaGetSymbolAddress((void**)&bufB,  g_bufB);

    // ---- SA1: npoint=512, r=0.2, K=32, MLP 3->64->64->128 ----
    prep_pts_kernel<<<(BB*NN+255)/256, 256>>>(x, pts1, BB*NN);
    fps_kernel<8><<<BB, 512>>>(x, NN, 512, fidx1, nxyz1);
    ball_kernel<32><<<(BB*512)/8, 256>>>(pts1, nxyz1, NN, 512, 0.04f, idx1);
    build_g1_kernel<<<(BB*512*32+255)/256, 256>>>(x, nxyz1, idx1, bufA);
    tgemm(bufA, w1[0], b1[0], bufB, 524288,  64,   3, 1);
    tgemm(bufB, w1[1], b1[1], bufA, 524288,  64,  64, 1);
    tgemm(bufA, w1[2], b1[2], bufB, 524288, 128,  64, 1);
    maxpool_kernel<<<(16384*128+255)/256, 256>>>(bufB, feat1, 16384, 32, 128);

    // ---- SA2: npoint=128, r=0.4, K=64, MLP 131->128->128->256 ----
    prep_pts_kernel<<<(BB*512+255)/256, 256>>>(nxyz1, pts2, BB*512);
    fps_kernel<1><<<BB, 512>>>(nxyz1, 512, 128, fidx2, nxyz2);
    ball_kernel<64><<<(BB*128)/8, 256>>>(pts2, nxyz2, 512, 128, 0.16f, idx2);
    {
        long long total = (long long)262144*131;
        int blocks = (int)((total + 255)/256);
        build_g2_kernel<<<blocks, 256>>>(nxyz1, feat1, nxyz2, idx2, bufA);
    }
    tgemm(bufA, w2[0], b2[0], bufB, 262144, 128, 131, 1);
    tgemm(bufB, w2[1], b2[1], bufA, 262144, 128, 128, 1);
    tgemm(bufA, w2[2], b2[2], bufB, 262144, 256, 128, 1);
    maxpool_kernel<<<(4096*256+255)/256, 256>>>(bufB, feat2, 4096, 64, 256);

    // ---- SA3 (group all): MLP 259->256->512->1024, max over 128 ----
    build_g3_kernel<<<(4096*259+255)/256, 256>>>(nxyz2, feat2, bufA);
    tgemm(bufA, w3[0], b3[0], bufB, 4096,  256, 259, 1);
    tgemm(bufB, w3[1], b3[1], bufA, 4096,  512, 256, 1);
    tgemm(bufA, w3[2], b3[2], bufB, 4096, 1024, 512, 1);
    maxpool_kernel<<<(32*1024+255)/256, 256>>>(bufB, feat3, 32, 128, 1024);

    // ---- FC head + softmax ----
    tgemm(feat3, fc1w, fc1b, fc1o,  32, 512, 1024, 1);
    tgemm(fc1o,  fc2w, fc2b, fc2o,  32, 256,  512, 1);
    tgemm(fc2o,  fc3w, fc3b, logits,32,  40,  256, 0);
    softmax_kernel<<<1, dim3(32,32)>>>(logits, (float*)d_out);
}

// round 4
// speedup vs baseline: 1.3200x; 1.3200x over previous
#include <cuda_runtime.h>
#include <math.h>
#include <stdint.h>

#define BB 32
#define NN 4096

typedef unsigned long long u64;

// ---------------- static device scratch (no allocations allowed) ----------------
__device__ float4 g_pts1[BB*NN];
__device__ float4 g_pts2[BB*512];
__device__ int    g_fidx1[BB*512];
__device__ float  g_nxyz1[BB*512*3];
__device__ int    g_idx1[BB*512*32];
__device__ int    g_fidx2[BB*128];
__device__ float  g_nxyz2[BB*128*3];
__device__ int    g_idx2[BB*128*64];
__device__ float  g_feat1[BB*512*128];
__device__ float  g_feat2[BB*128*256];
__device__ float  g_feat3[BB*1024];
__device__ float  g_fc1o[BB*512];
__device__ float  g_fc2o[BB*256];
__device__ float  g_logits[BB*64];
__device__ float  g_zerob[1024];          // stays zero (never written)
__device__ float  g_wts[2097152];         // transposed weights arena (8 MiB)
__device__ float  g_bufA[67108864];       // 256 MiB ping
__device__ float  g_bufB[67108864];       // 256 MiB pong

// no-FMA fp32 helpers (must match XLA's elementwise mul/add ordering)
__device__ __forceinline__ float fm(float a, float b){ return __fmul_rn(a,b); }
__device__ __forceinline__ float fa(float a, float b){ return __fadd_rn(a,b); }

// packed f32x2 helpers
__device__ __forceinline__ u64 pack2(float x){
    u64 r; asm("mov.b64 %0, {%1, %1};" : "=l"(r) : "f"(x)); return r;
}
__device__ __forceinline__ void fma2(u64& c, u64 a, u64 b){
    asm("fma.rn.f32x2 %0, %1, %2, %0;" : "+l"(c) : "l"(a), "l"(b));
}
__device__ __forceinline__ float2 unpack2(u64 v){
    float2 f; asm("mov.b64 {%0, %1}, %2;" : "=f"(f.x), "=f"(f.y) : "l"(v)); return f;
}

// ---------------- pack xyz + sumsq into float4 for ball query ----------------
__global__ void prep_pts_kernel(const float* __restrict__ xyz, float4* __restrict__ pts, int total){
    int i = blockIdx.x*blockDim.x + threadIdx.x;
    if (i >= total) return;
    float x = xyz[i*3+0], y = xyz[i*3+1], z = xyz[i*3+2];
    pts[i] = make_float4(x, y, z, fa(fa(fm(x,x), fm(y,y)), fm(z,z)));
}

// ---------------- farthest point sampling: one block per batch ----------------
template<int PPT>
__global__ void fps_kernel(const float* __restrict__ xyz, int n, int m,
                           int* __restrict__ fidx, float* __restrict__ nxyz){
    const int T = 512;
    int b = blockIdx.x, tid = threadIdx.x;
    const float* p = xyz + (size_t)b*n*3;
    float px[PPT], py[PPT], pz[PPT], mind[PPT];
    #pragma unroll
    for (int i=0;i<PPT;i++){
        int j = tid + i*T;
        if (j < n){ px[i]=p[j*3]; py[i]=p[j*3+1]; pz[i]=p[j*3+2]; mind[i]=1e10f; }
        else mind[i] = -1e30f;
    }
    __shared__ float sv[16];
    __shared__ int   si[16];
    __shared__ float cur[3];
    __shared__ int   slast;
    int last = 0;
    for (int t=0;t<m;t++){
        if (tid == 0){
            fidx[b*m+t] = last;
            float cx=p[last*3], cy=p[last*3+1], cz=p[last*3+2];
            cur[0]=cx; cur[1]=cy; cur[2]=cz;
            nxyz[((size_t)b*m+t)*3+0]=cx;
            nxyz[((size_t)b*m+t)*3+1]=cy;
            nxyz[((size_t)b*m+t)*3+2]=cz;
        }
        __syncthreads();
        float cx=cur[0], cy=cur[1], cz=cur[2];
        float bv=-1e30f; int bj=0x7fffffff;
        #pragma unroll
        for (int i=0;i<PPT;i++){
            int j = tid + i*T;
            if (j < n){
                float dx=px[i]-cx, dy=py[i]-cy, dz=pz[i]-cz;
                float d = fa(fa(fm(dx,dx), fm(dy,dy)), fm(dz,dz));
                float mn = fminf(mind[i], d);
                mind[i] = mn;
                if (mn > bv){ bv=mn; bj=j; }
            }
        }
        #pragma unroll
        for (int off=16; off; off>>=1){
            float ov = __shfl_down_sync(0xffffffffu, bv, off);
            int   oj = __shfl_down_sync(0xffffffffu, bj, off);
            if (ov > bv || (ov == bv && oj < bj)){ bv=ov; bj=oj; }
        }
        if ((tid&31)==0){ sv[tid>>5]=bv; si[tid>>5]=bj; }
        __syncthreads();
        if (tid < 32){
            float v = (tid<16)? sv[tid] : -1e30f;
            int   j = (tid<16)? si[tid] : 0x7fffffff;
            #pragma unroll
            for (int off=16; off; off>>=1){
                float ov = __shfl_down_sync(0xffffffffu, v, off);
                int   oj = __shfl_down_sync(0xffffffffu, j, off);
                if (ov > v || (ov == v && oj < j)){ v=ov; j=oj; }
            }
            if (tid==0) slast = j;
        }
        __syncthreads();
        last = slast;
    }
}

// ---------------- ball query: one warp per centroid ----------------
template<int KS>
__global__ void ball_kernel(const float4* __restrict__ pts, const float* __restrict__ nxyz,
                            int n, int S, float r2, int* __restrict__ out){
    __shared__ int widx[8][KS];
    int w = threadIdx.x >> 5, lane = threadIdx.x & 31;
    int sg = blockIdx.x*8 + w;
    int b = sg / S;
    const float4* P = pts + (size_t)b*n;
    float cx = nxyz[(size_t)sg*3+0], cy = nxyz[(size_t)sg*3+1], cz = nxyz[(size_t)sg*3+2];
    float sn = fa(fa(fm(cx,cx), fm(cy,cy)), fm(cz,cz));
    int cnt = 0;
    for (int j0=0; j0<n && cnt<KS; j0+=32){
        int j = j0 + lane;
        float4 q = P[j];
        float dot = fa(fa(fm(cx,q.x), fm(cy,q.y)), fm(cz,q.z));
        float sqd = __fsub_rn(fa(sn, q.w), fm(2.0f, dot));
        bool inb = (sqd <= r2);
        unsigned msk = __ballot_sync(0xffffffffu, inb);
        int pos = cnt + __popc(msk & ((1u<<lane)-1u));
        if (inb && pos < KS) widx[w][pos] = j;
        cnt += __popc(msk);
    }
    __syncwarp();
    int c = cnt < KS ? cnt : KS;
    int first = widx[w][0];
    for (int p = c + lane; p < KS; p += 32) widx[w][p] = first;
    __syncwarp();
    for (int p = lane; p < KS; p += 32) out[(size_t)sg*KS + p] = widx[w][p];
}

// ---------------- weight transpose (with optional col offset + K padding) ----------------
__global__ void transpose_w_kernel(const float* __restrict__ W, float* __restrict__ Wt,
                                   int stride, int koff, int K, int Kpad, int N){
    int e = blockIdx.x*blockDim.x + threadIdx.x;
    if (e >= Kpad*N) return;
    int k = e / N, n = e % N;
    Wt[e] = (k < K) ? W[(size_t)n*stride + koff + k] : 0.f;
}

// ---------------- fused SA1 grouping + layer0 (K=3) ----------------
__global__ void fused_g1l0_kernel(const float* __restrict__ x, const float* __restrict__ nxyz,
                                  const int* __restrict__ idx, const float* __restrict__ W,
                                  const float* __restrict__ b, float* __restrict__ out){
    __shared__ float sW[192], sB[64];
    int tid = threadIdx.x;
    if (tid < 192) sW[tid] = W[tid];
    if (tid < 64)  sB[tid] = b[tid];
    __syncthreads();
    int r = blockIdx.x*64 + (tid>>2);
    int q = tid & 3;
    int s = (r>>5) & 511, bb = r >> 14;
    int j = idx[r];
    const float* pp = x    + ((size_t)bb*NN  + j)*3;
    const float* cc = nxyz + ((size_t)bb*512 + s)*3;
    float dx = pp[0]-cc[0], dy = pp[1]-cc[1], dz = pp[2]-cc[2];
    float o[16];
    #pragma unroll
    for (int u=0; u<16; u++){
        int n = q*16 + u;
        float v = fmaf(sW[n*3], dx, fmaf(sW[n*3+1], dy, fmaf(sW[n*3+2], dz, sB[n])));
        o[u] = fmaxf(v, 0.f);
    }
    float4* po = (float4*)(out + (size_t)r*64 + q*16);
    #pragma unroll
    for (int u=0; u<4; u++) po[u] = make_float4(o[u*4], o[u*4+1], o[u*4+2], o[u*4+3]);
}

// ---------------- fused SA2 gather + layer1 combine (factorized) ----------------
// out[r] = relu(F[gather j] + W0xyz*dxyz + bias)
__global__ void fused_gather2_kernel(const float* __restrict__ F, const float* __restrict__ nxyz1,
                                     const float* __restrict__ nxyz2, const int* __restrict__ idx,
                                     const float* __restrict__ W, const float* __restrict__ b,
                                     float* __restrict__ out){
    __shared__ float sWx[384], sB[128];
    int tid = threadIdx.x;
    if (tid < 128){
        sB[tid] = b[tid];
        sWx[tid*3+0] = W[(size_t)tid*131 + 0];
        sWx[tid*3+1] = W[(size_t)tid*131 + 1];
        sWx[tid*3+2] = W[(size_t)tid*131 + 2];
    }
    __syncthreads();
    int r = blockIdx.x*64 + (tid>>2);
    int q = tid & 3;
    int s = (r>>6) & 127, bb = r >> 13;
    int j = idx[r];
    const float* cc = nxyz2 + ((size_t)bb*128 + s)*3;
    const float* pp = nxyz1 + ((size_t)bb*512 + j)*3;
    float dx = pp[0]-cc[0], dy = pp[1]-cc[1], dz = pp[2]-cc[2];
    const float* Fr = F + ((size_t)bb*512 + j)*128 + q*32;
    float* po = out + (size_t)r*128 + q*32;
    #pragma unroll
    for (int u=0; u<32; u+=4){
        float4 f = *(const float4*)(Fr + u);
        int n = q*32 + u;
        float v0 = fmaf(sWx[(n+0)*3],dx, fmaf(sWx[(n+0)*3+1],dy, fmaf(sWx[(n+0)*3+2],dz, f.x + sB[n+0])));
        float v1 = fmaf(sWx[(n+1)*3],dx, fmaf(sWx[(n+1)*3+1],dy, fmaf(sWx[(n+1)*3+2],dz, f.y + sB[n+1])));
        float v2 = fmaf(sWx[(n+2)*3],dx, fmaf(sWx[(n+2)*3+1],dy, fmaf(sWx[(n+2)*3+2],dz, f.z + sB[n+2])));
        float v3 = fmaf(sWx[(n+3)*3],dx, fmaf(sWx[(n+3)*3+1],dy, fmaf(sWx[(n+3)*3+2],dz, f.w + sB[n+3])));
        *(float4*)(po + u) = make_float4(fmaxf(v0,0.f), fmaxf(v1,0.f), fmaxf(v2,0.f), fmaxf(v3,0.f));
    }
}

// ---------------- build g3 (zero-padded to stride 272) ----------------
__global__ void build_g3_kernel(const float* __restrict__ nxyz2, const float* __restrict__ feat2,
                                float* __restrict__ g){
    int e = blockIdx.x*blockDim.x + threadIdx.x;
    if (e >= 4096*272) return;
    int c = e % 272, r = e / 272;
    float v = (c<3) ? nxyz2[(size_t)r*3+c] : ((c<259) ? feat2[(size_t)r*256 + (c-3)] : 0.f);
    g[e] = v;
}

// ---------------- max pool over group dim ----------------
__global__ void maxpool_kernel(const float* __restrict__ in, float* __restrict__ out,
                               int G, int Kp, int C){
    int e = blockIdx.x*blockDim.x + threadIdx.x;
    if (e >= G*C) return;
    int g = e / C, c = e % C;
    const float* p = in + (size_t)g*Kp*C + c;
    float v = p[0];
    for (int k=1;k<Kp;k++) v = fmaxf(v, p[(size_t)k*C]);
    out[(size_t)g*C + c] = v;
}

// ---------------- packed-f32x2 SGEMM ----------------
// C[M,N] = relu?(A[M,K] @ Wt[K,N] + bias), Wt is pre-transposed (k-major).
// Block 128 x BN, BK=16, 256 threads. Warps 4(m) x 2(n); thread 8(m) x 4(n);
// per-thread micro-tile 4m x (BN/8)n held as f32x2 pairs -> FFMA2.
template<int BN>
__global__ void __launch_bounds__(256, 2)
f2gemm_kernel(const float* __restrict__ A, const float* __restrict__ Wt,
              const float* __restrict__ bias, float* __restrict__ C,
              long long M, int N, int K, int doRelu)
{
    constexpr int NP  = BN/16;          // f32x2 pairs per thread (8 or 4)
    constexpr int TNW = BN/8;           // per-thread n extent in floats (16 or 8)
    constexpr int NB4 = (BN*16)/1024;   // B float4 loads per thread (2 or 1)
    __shared__ __align__(16) float As[128*20];
    __shared__ __align__(16) float Bs[16*BN];

    const int tid = threadIdx.x, lane = tid & 31, wid = tid >> 5;
    const int wm = (wid & 3)*32, wn = (wid >> 2)*(BN/2);
    const int tm = lane >> 2,  tn = lane & 3;
    const long long bm = (long long)blockIdx.y * 128;
    const int bn = blockIdx.x * BN;

    u64 acc[4][NP];
    #pragma unroll
    for (int i=0;i<4;i++)
        #pragma unroll
        for (int p=0;p<NP;p++) acc[i][p] = 0ull;

    uint4 ra[2], rb[NB4];

    auto ldg = [&](int k0){
        #pragma unroll
        for (int p=0;p<2;p++){
            int idx = tid + p*256;
            int m = idx >> 2, kq = idx & 3;
            long long gm = bm + m;
            ra[p] = (gm < M) ? *(const uint4*)(A + gm*(long long)K + k0 + kq*4)
                             : make_uint4(0,0,0,0);
        }
        #pragma unroll
        for (int p=0;p<NB4;p++){
            int idx = tid + p*256;
            int k = idx / (BN/4), nq = idx % (BN/4);
            int gn = bn + nq*4;
            rb[p] = (gn < N) ? *(const uint4*)(Wt + (size_t)(k0+k)*N + gn)
                             : make_uint4(0,0,0,0);
        }
    };
    auto sts = [&](){
        #pragma unroll
        for (int p=0;p<2;p++){
            int idx = tid + p*256;
            int m = idx >> 2, kq = idx & 3;
            *(uint4*)(As + m*20 + kq*4) = ra[p];
        }
        #pragma unroll
        for (int p=0;p<NB4;p++){
            int idx = tid + p*256;
            int k = idx / (BN/4), nq = idx % (BN/4);
            *(uint4*)(Bs + k*BN + nq*4) = rb[p];
        }
    };

    const int T = K / 16;
    ldg(0); sts(); __syncthreads();
    for (int t=0; t<T; t++){
        if (t+1 < T) ldg((t+1)*16);
        #pragma unroll
        for (int kk=0; kk<16; kk++){
            u64 a2[4];
            #pragma unroll
            for (int i=0;i<4;i++)
                a2[i] = pack2(As[(wm + tm + 8*i)*20 + kk]);
            u64 b2[NP];
            #pragma unroll
            for (int j=0;j<NP/2;j++){
                ulonglong2 v = *(const ulonglong2*)(Bs + kk*BN + wn + tn*TNW + j*4);
                b2[2*j]   = v.x;
                b2[2*j+1] = v.y;
            }
            #pragma unroll
            for (int i=0;i<4;i++)
                #pragma unroll
                for (int p=0;p<NP;p++)
                    fma2(acc[i][p], a2[i], b2[p]);
        }
        __syncthreads();
        if (t+1 < T){ sts(); __syncthreads(); }
    }

    // epilogue
    const int n0 = bn + wn + tn*TNW;
    #pragma unroll
    for (int i=0;i<4;i++){
        long long gm = bm + wm + tm + 8*i;
        if (gm >= M) continue;
        #pragma unroll
        for (int j=0;j<NP/2;j++){
            int gn = n0 + j*4;
            if (gn >= N) continue;           // N % 4 == 0 always
            float4 bv = *(const float4*)(bias + gn);
            float2 p0 = unpack2(acc[i][2*j]);
            float2 p1 = unpack2(acc[i][2*j+1]);
            float4 o;
            o.x = p0.x + bv.x; o.y = p0.y + bv.y;
            o.z = p1.x + bv.z; o.w = p1.y + bv.w;
            if (doRelu){
                o.x = fmaxf(o.x,0.f); o.y = fmaxf(o.y,0.f);
                o.z = fmaxf(o.z,0.f); o.w = fmaxf(o.w,0.f);
            }
            *(float4*)(C + gm*(long long)N + gn) = o;
        }
    }
}

// ---------------- softmax over 40 classes, 32 rows ----------------
__global__ void softmax_kernel(const float* __restrict__ in, float* __restrict__ out){
    int b = threadIdx.y;
    int lane = threadIdx.x;
    float v0 = in[b*40 + lane];
    float v1 = (lane < 8) ? in[b*40 + lane + 32] : -INFINITY;
    float mx = fmaxf(v0, v1);
    #pragma unroll
    for (int off=16; off; off>>=1) mx = fmaxf(mx, __shfl_xor_sync(0xffffffffu, mx, off));
    float e0 = expf(v0 - mx);
    float e1 = (lane < 8) ? expf(v1 - mx) : 0.f;
    float sm = e0 + e1;
    #pragma unroll
    for (int off=16; off; off>>=1) sm += __shfl_xor_sync(0xffffffffu, sm, off);
    out[b*40 + lane] = e0 / sm;
    if (lane < 8) out[b*40 + lane + 32] = e1 / sm;
}

// ---------------- host side ----------------
static void f2gemm(const float* A, const float* Wt, const float* bias, float* C,
                   long long M, int N, int K, int doRelu)
{
    int gy = (int)((M + 127)/128);
    if (N >= 128){
        dim3 grid(N/128, gy);
        f2gemm_kernel<128><<<grid, 256>>>(A, Wt, bias, C, M, N, K, doRelu);
    } else {
        dim3 grid((N+63)/64, gy);
        f2gemm_kernel<64><<<grid, 256>>>(A, Wt, bias, C, M, N, K, doRelu);
    }
}

static void transW(const float* W, float* Wt, int stride, int koff, int K, int Kpad, int N){
    int tot = Kpad*N;
    transpose_w_kernel<<<(tot+255)/256, 256>>>(W, Wt, stride, koff, K, Kpad, N);
}

extern "C" void kernel_launch(void* const* d_in, const int* in_sizes, int n_in,
                              void* d_out, int out_size)
{
    (void)in_sizes; (void)n_in; (void)out_size;
    const float* x    = (const float*)d_in[0];
    const float* w1[3]= {(const float*)d_in[1],(const float*)d_in[3],(const float*)d_in[5]};
    const float* b1[3]= {(const float*)d_in[2],(const float*)d_in[4],(const float*)d_in[6]};
    const float* w2[3]= {(const float*)d_in[7],(const float*)d_in[9],(const float*)d_in[11]};
    const float* b2[3]= {(const float*)d_in[8],(const float*)d_in[10],(const float*)d_in[12]};
    const float* w3[3]= {(const float*)d_in[13],(const float*)d_in[15],(const float*)d_in[17]};
    const float* b3[3]= {(const float*)d_in[14],(const float*)d_in[16],(const float*)d_in[18]};
    const float* fc1w=(const float*)d_in[19]; const float* fc1b=(const float*)d_in[20];
    const float* fc2w=(const float*)d_in[21]; const float* fc2b=(const float*)d_in[22];
    const float* fc3w=(const float*)d_in[23]; const float* fc3b=(const float*)d_in[24];

    float4 *pts1, *pts2;
    int *fidx1, *fidx2, *idx1, *idx2;
    float *nxyz1, *nxyz2, *feat1, *feat2, *feat3, *fc1o, *fc2o, *logits, *zerob, *wts, *bufA, *bufB;
    cudaGetSymbolAddress((void**)&pts1,  g_pts1);
    cudaGetSymbolAddress((void**)&pts2,  g_pts2);
    cudaGetSymbolAddress((void**)&fidx1, g_fidx1);
    cudaGetSymbolAddress((void**)&nxyz1, g_nxyz1);
    cudaGetSymbolAddress((void**)&idx1,  g_idx1);
    cudaGetSymbolAddress((void**)&fidx2, g_fidx2);
    cudaGetSymbolAddress((void**)&nxyz2, g_nxyz2);
    cudaGetSymbolAddress((void**)&idx2,  g_idx2);
    cudaGetSymbolAddress((void**)&feat1, g_feat1);
    cudaGetSymbolAddress((void**)&feat2, g_feat2);
    cudaGetSymbolAddress((void**)&feat3, g_feat3);
    cudaGetSymbolAddress((void**)&fc1o,  g_fc1o);
    cudaGetSymbolAddress((void**)&fc2o,  g_fc2o);
    cudaGetSymbolAddress((void**)&logits,g_logits);
    cudaGetSymbolAddress((void**)&zerob, g_zerob);
    cudaGetSymbolAddress((void**)&wts,   g_wts);
    cudaGetSymbolAddress((void**)&bufA,  g_bufA);
    cudaGetSymbolAddress((void**)&bufB,  g_bufB);

    // transposed-weight arena offsets
    float* wt11  = wts + 0;        // K=64  N=64
    float* wt12  = wts + 4096;     // K=64  N=128
    float* wt20f = wts + 12288;    // K=128 N=128 (cols 3..130 of w2_0)
    float* wt21  = wts + 28672;    // K=128 N=128
    float* wt22  = wts + 45056;    // K=128 N=256
    float* wt30  = wts + 77824;    // Kpad=272 N=256
    float* wt31  = wts + 147456;   // K=256 N=512
    float* wt32  = wts + 278528;   // K=512 N=1024
    float* fc1t  = wts + 802816;   // K=1024 N=512
    float* fc2t  = wts + 1327104;  // K=512 N=256
    float* fc3t  = wts + 1458176;  // K=256 N=40

    // ---- weight transposes ----
    transW(w1[1],  wt11,   64, 0,  64,  64,  64);
    transW(w1[2],  wt12,   64, 0,  64,  64, 128);
    transW(w2[0],  wt20f, 131, 3, 128, 128, 128);
    transW(w2[1],  wt21,  128, 0, 128, 128, 128);
    transW(w2[2],  wt22,  128, 0, 128, 128, 256);
    transW(w3[0],  wt30,  259, 0, 259, 272, 256);
    transW(w3[1],  wt31,  256, 0, 256, 256, 512);
    transW(w3[2],  wt32,  512, 0, 512, 512, 1024);
    transW(fc1w,   fc1t, 1024, 0,1024,1024, 512);
    transW(fc2w,   fc2t,  512, 0, 512, 512, 256);
    transW(fc3w,   fc3t,  256, 0, 256, 256,  40);

    // ---- SA1: npoint=512, r=0.2, K=32, MLP 3->64->64->128 ----
    prep_pts_kernel<<<(BB*NN+255)/256, 256>>>(x, pts1, BB*NN);
    fps_kernel<8><<<BB, 512>>>(x, NN, 512, fidx1, nxyz1);
    ball_kernel<32><<<(BB*512)/8, 256>>>(pts1, nxyz1, NN, 512, 0.04f, idx1);
    fused_g1l0_kernel<<<524288/64, 256>>>(x, nxyz1, idx1, w1[0], b1[0], bufB);
    f2gemm(bufB, wt11, b1[1], bufA, 524288,  64,  64, 1);
    f2gemm(bufA, wt12, b1[2], bufB, 524288, 128,  64, 1);
    maxpool_kernel<<<(16384*128+255)/256, 256>>>(bufB, feat1, 16384, 32, 128);

    // ---- SA2: npoint=128, r=0.4, K=64, MLP 131->128->128->256 (layer1 factorized) ----
    prep_pts_kernel<<<(BB*512+255)/256, 256>>>(nxyz1, pts2, BB*512);
    fps_kernel<1><<<BB, 512>>>(nxyz1, 512, 128, fidx2, nxyz2);
    ball_kernel<64><<<(BB*128)/8, 256>>>(pts2, nxyz2, 512, 128, 0.16f, idx2);
    f2gemm(feat1, wt20f, zerob, bufA, 16384, 128, 128, 0);   // F = feat1 @ W0f^T
    fused_gather2_kernel<<<262144/64, 256>>>(bufA, nxyz1, nxyz2, idx2, w2[0], b2[0], bufB);
    f2gemm(bufB, wt21, b2[1], bufA, 262144, 128, 128, 1);
    f2gemm(bufA, wt22, b2[2], bufB, 262144, 256, 128, 1);
    maxpool_kernel<<<(4096*256+255)/256, 256>>>(bufB, feat2, 4096, 64, 256);

    // ---- SA3 (group all): MLP 259->256->512->1024, max over 128 ----
    build_g3_kernel<<<(4096*272+255)/256, 256>>>(nxyz2, feat2, bufA);
    f2gemm(bufA, wt30, b3[0], bufB, 4096,  256, 272, 1);
    f2gemm(bufB, wt31, b3[1], bufA, 4096,  512, 256, 1);
    f2gemm(bufA, wt32, b3[2], bufB, 4096, 1024, 512, 1);
    maxpool_kernel<<<(32*1024+255)/256, 256>>>(bufB, feat3, 32, 128, 1024);

    // ---- FC head + softmax ----
    f2gemm(feat3, fc1t, fc1b, fc1o,  32, 512, 1024, 1);
    f2gemm(fc1o,  fc2t, fc2b, fc2o,  32, 256,  512, 1);
    f2gemm(fc2o,  fc3t, fc3b, logits,32,  40,  256, 0);
    softmax_kernel<<<1, dim3(32,32)>>>(logits, (float*)d_out);
}

// round 10
// speedup vs baseline: 1.9647x; 1.4884x over previous
#include <cuda_runtime.h>
#include <cuda_bf16.h>
#include <math.h>
#include <stdint.h>

#define BB 32
#define NN 4096

typedef unsigned long long u64;

// ---------------- static device scratch (no allocations allowed) ----------------
__device__ float4 g_pts1[BB*NN];
__device__ float4 g_pts2[BB*512];
__device__ int    g_fidx1[BB*512];
__device__ float  g_nxyz1[BB*512*3];
__device__ int    g_idx1[BB*512*32];
__device__ int    g_fidx2[BB*128];
__device__ float  g_nxyz2[BB*128*3];
__device__ int    g_idx2[BB*128*64];
__device__ float  g_feat1[BB*512*128];
__device__ float  g_feat2[BB*128*256];
__device__ float  g_feat3[BB*1024];
__device__ float  g_fc1o[BB*512];
__device__ float  g_fc2o[BB*256];
__device__ float  g_logits[BB*64];
__device__ float  g_zerob[1024];          // stays zero (never written)
__device__ float  g_wts[2097152];         // transposed fp32 weights (f2gemm path)
__device__ float  g_bufA[67108864];       // 256 MiB ping (fp32)
__device__ float  g_bufB[67108864];       // 256 MiB pong (fp32)
// bf16 hi/lo split activation ping-pong + weights
__device__ __nv_bfloat16 g_sAhi[33554432];
__device__ __nv_bfloat16 g_sAlo[33554432];
__device__ __nv_bfloat16 g_sBhi[33554432];
__device__ __nv_bfloat16 g_sBlo[33554432];
__device__ __nv_bfloat16 g_wbhi[1048576];
__device__ __nv_bfloat16 g_wblo[1048576];

// no-FMA fp32 helpers (must match XLA's elementwise mul/add ordering)
__device__ __forceinline__ float fm(float a, float b){ return __fmul_rn(a,b); }
__device__ __forceinline__ float fa(float a, float b){ return __fadd_rn(a,b); }

// packed f32x2 helpers (f2gemm path)
__device__ __forceinline__ u64 pack2(float x){
    u64 r; asm("mov.b64 %0, {%1, %1};" : "=l"(r) : "f"(x)); return r;
}
__device__ __forceinline__ void fma2(u64& c, u64 a, u64 b){
    asm("fma.rn.f32x2 %0, %1, %2, %0;" : "+l"(c) : "l"(a), "l"(b));
}
__device__ __forceinline__ float2 unpack2(u64 v){
    float2 f; asm("mov.b64 {%0, %1}, %2;" : "=f"(f.x), "=f"(f.y) : "l"(v)); return f;
}

// bf16 split helpers
__device__ __forceinline__ void splitbf(float v, __nv_bfloat16& h, __nv_bfloat16& l){
    h = __float2bfloat16(v);
    l = __float2bfloat16(v - __bfloat162float(h));
}
__device__ __forceinline__ uint32_t packbf(__nv_bfloat16 a, __nv_bfloat16 b){
    return (uint32_t)__bfloat16_as_ushort(a) | ((uint32_t)__bfloat16_as_ushort(b) << 16);
}

// bf16 tensor-core mma (m16n8k16), fp32 accumulate
#define MMA_BF16(c, a0,a1,a2,a3, b0,b1) \
  asm volatile("mma.sync.aligned.m16n8k16.row.col.f32.bf16.bf16.f32 " \
    "{%0,%1,%2,%3}, {%4,%5,%6,%7}, {%8,%9}, {%0,%1,%2,%3};" \
    : "+f"((c)[0]),"+f"((c)[1]),"+f"((c)[2]),"+f"((c)[3]) \
    : "r"(a0),"r"(a1),"r"(a2),"r"(a3),"r"(b0),"r"(b1))

// ---------------- pack xyz + sumsq into float4 for ball query ----------------
__global__ void prep_pts_kernel(const float* __restrict__ xyz, float4* __restrict__ pts, int total){
    int i = blockIdx.x*blockDim.x + threadIdx.x;
    if (i >= total) return;
    float x = xyz[i*3+0], y = xyz[i*3+1], z = xyz[i*3+2];
    pts[i] = make_float4(x, y, z, fa(fa(fm(x,x), fm(y,y)), fm(z,z)));
}

// ---------------- farthest point sampling: one block per batch ----------------
template<int PPT>
__global__ void fps_kernel(const float* __restrict__ xyz, int n, int m,
                           int* __restrict__ fidx, float* __restrict__ nxyz){
    const int T = 512;
    int b = blockIdx.x, tid = threadIdx.x;
    const float* p = xyz + (size_t)b*n*3;
    float px[PPT], py[PPT], pz[PPT], mind[PPT];
    #pragma unroll
    for (int i=0;i<PPT;i++){
        int j = tid + i*T;
        if (j < n){ px[i]=p[j*3]; py[i]=p[j*3+1]; pz[i]=p[j*3+2]; mind[i]=1e10f; }
        else mind[i] = -1e30f;
    }
    __shared__ float sv[16];
    __shared__ int   si[16];
    __shared__ float cur[3];
    __shared__ int   slast;
    int last = 0;
    for (int t=0;t<m;t++){
        if (tid == 0){
            fidx[b*m+t] = last;
            float cx=p[last*3], cy=p[last*3+1], cz=p[last*3+2];
            cur[0]=cx; cur[1]=cy; cur[2]=cz;
            nxyz[((size_t)b*m+t)*3+0]=cx;
            nxyz[((size_t)b*m+t)*3+1]=cy;
            nxyz[((size_t)b*m+t)*3+2]=cz;
        }
        __syncthreads();
        float cx=cur[0], cy=cur[1], cz=cur[2];
        float bv=-1e30f; int bj=0x7fffffff;
        #pragma unroll
        for (int i=0;i<PPT;i++){
            int j = tid + i*T;
            if (j < n){
                float dx=px[i]-cx, dy=py[i]-cy, dz=pz[i]-cz;
                float d = fa(fa(fm(dx,dx), fm(dy,dy)), fm(dz,dz));
                float mn = fminf(mind[i], d);
                mind[i] = mn;
                if (mn > bv){ bv=mn; bj=j; }
            }
        }
        #pragma unroll
        for (int off=16; off; off>>=1){
            float ov = __shfl_down_sync(0xffffffffu, bv, off);
            int   oj = __shfl_down_sync(0xffffffffu, bj, off);
            if (ov > bv || (ov == bv && oj < bj)){ bv=ov; bj=oj; }
        }
        if ((tid&31)==0){ sv[tid>>5]=bv; si[tid>>5]=bj; }
        __syncthreads();
        if (tid < 32){
            float v = (tid<16)? sv[tid] : -1e30f;
            int   j = (tid<16)? si[tid] : 0x7fffffff;
            #pragma unroll
            for (int off=16; off; off>>=1){
                float ov = __shfl_down_sync(0xffffffffu, v, off);
                int   oj = __shfl_down_sync(0xffffffffu, j, off);
                if (ov > v || (ov == v && oj < j)){ v=ov; j=oj; }
            }
            if (tid==0) slast = j;
        }
        __syncthreads();
        last = slast;
    }
}

// ---------------- ball query: one warp per centroid ----------------
template<int KS>
__global__ void ball_kernel(const float4* __restrict__ pts, const float* __restrict__ nxyz,
                            int n, int S, float r2, int* __restrict__ out){
    __shared__ int widx[8][KS];
    int w = threadIdx.x >> 5, lane = threadIdx.x & 31;
    int sg = blockIdx.x*8 + w;
    int b = sg / S;
    const float4* P = pts + (size_t)b*n;
    float cx = nxyz[(size_t)sg*3+0], cy = nxyz[(size_t)sg*3+1], cz = nxyz[(size_t)sg*3+2];
    float sn = fa(fa(fm(cx,cx), fm(cy,cy)), fm(cz,cz));
    int cnt = 0;
    for (int j0=0; j0<n && cnt<KS; j0+=32){
        int j = j0 + lane;
        float4 q = P[j];
        float dot = fa(fa(fm(cx,q.x), fm(cy,q.y)), fm(cz,q.z));
        float sqd = __fsub_rn(fa(sn, q.w), fm(2.0f, dot));
        bool inb = (sqd <= r2);
        unsigned msk = __ballot_sync(0xffffffffu, inb);
        int pos = cnt + __popc(msk & ((1u<<lane)-1u));
        if (inb && pos < KS) widx[w][pos] = j;
        cnt += __popc(msk);
    }
    __syncwarp();
    int c = cnt < KS ? cnt : KS;
    int first = widx[w][0];
    for (int p = c + lane; p < KS; p += 32) widx[w][p] = first;
    __syncwarp();
    for (int p = lane; p < KS; p += 32) out[(size_t)sg*KS + p] = widx[w][p];
}

// ---------------- weight transpose (f2gemm path) ----------------
__global__ void transpose_w_kernel(const float* __restrict__ W, float* __restrict__ Wt,
                                   int stride, int koff, int K, int Kpad, int N){
    int e = blockIdx.x*blockDim.x + threadIdx.x;
    if (e >= Kpad*N) return;
    int k = e / N, n = e % N;
    Wt[e] = (k < K) ? W[(size_t)n*stride + koff + k] : 0.f;
}

// ---------------- weight hi/lo split (mma path; keeps [N,K] K-major, pads K) ----------------
__global__ void split_w_kernel(const float* __restrict__ W, __nv_bfloat16* __restrict__ hi,
                               __nv_bfloat16* __restrict__ lo, int Kin, int Kpad, int N){
    int e = blockIdx.x*blockDim.x + threadIdx.x;
    if (e >= N*Kpad) return;
    int n = e / Kpad, k = e % Kpad;
    float v = (k < Kin) ? W[(size_t)n*Kin + k] : 0.f;
    __nv_bfloat16 h, l; splitbf(v, h, l);
    hi[e] = h; lo[e] = l;
}

// ---------------- fused SA1 grouping + layer0 (K=3), split bf16 output ----------------
__global__ void fused_g1l0s_kernel(const float* __restrict__ x, const float* __restrict__ nxyz,
                                   const int* __restrict__ idx, const float* __restrict__ W,
                                   const float* __restrict__ b,
                                   __nv_bfloat16* __restrict__ ohi, __nv_bfloat16* __restrict__ olo){
    __shared__ float sW[192], sB[64];
    int tid = threadIdx.x;
    if (tid < 192) sW[tid] = W[tid];
    if (tid < 64)  sB[tid] = b[tid];
    __syncthreads();
    int r = blockIdx.x*64 + (tid>>2);
    int q = tid & 3;
    int s = (r>>5) & 511, bb = r >> 14;
    int j = idx[r];
    const float* pp = x    + ((size_t)bb*NN  + j)*3;
    const float* cc = nxyz + ((size_t)bb*512 + s)*3;
    float dx = pp[0]-cc[0], dy = pp[1]-cc[1], dz = pp[2]-cc[2];
    uint32_t hw[8], lw[8];
    #pragma unroll
    for (int u=0; u<16; u+=2){
        int n = q*16 + u;
        float v0 = fmaxf(fmaf(sW[n*3],     dx, fmaf(sW[n*3+1],     dy, fmaf(sW[n*3+2],     dz, sB[n]  ))), 0.f);
        float v1 = fmaxf(fmaf(sW[(n+1)*3], dx, fmaf(sW[(n+1)*3+1], dy, fmaf(sW[(n+1)*3+2], dz, sB[n+1]))), 0.f);
        __nv_bfloat16 h0,l0,h1,l1; splitbf(v0,h0,l0); splitbf(v1,h1,l1);
        hw[u>>1] = packbf(h0,h1); lw[u>>1] = packbf(l0,l1);
    }
    size_t o = (size_t)r*64 + q*16;
    *(uint4*)(ohi + o)     = make_uint4(hw[0],hw[1],hw[2],hw[3]);
    *(uint4*)(ohi + o + 8) = make_uint4(hw[4],hw[5],hw[6],hw[7]);
    *(uint4*)(olo + o)     = make_uint4(lw[0],lw[1],lw[2],lw[3]);
    *(uint4*)(olo + o + 8) = make_uint4(lw[4],lw[5],lw[6],lw[7]);
}

// ---------------- fused SA2 gather + layer1 combine (factorized), split bf16 output ----------------
__global__ void fused_gather2s_kernel(const float* __restrict__ F, const float* __restrict__ nxyz1,
                                      const float* __restrict__ nxyz2, const int* __restrict__ idx,
                                      const float* __restrict__ W, const float* __restrict__ b,
                                      __nv_bfloat16* __restrict__ ohi, __nv_bfloat16* __restrict__ olo){
    __shared__ float sWx[384], sB[128];
    int tid = threadIdx.x;
    if (tid < 128){
        sB[tid] = b[tid];
        sWx[tid*3+0] = W[(size_t)tid*131 + 0];
        sWx[tid*3+1] = W[(size_t)tid*131 + 1];
        sWx[tid*3+2] = W[(size_t)tid*131 + 2];
    }
    __syncthreads();
    int r = blockIdx.x*64 + (tid>>2);
    int q = tid & 3;
    int s = (r>>6) & 127, bb = r >> 13;
    int j = idx[r];
    const float* cc = nxyz2 + ((size_t)bb*128 + s)*3;
    const float* pp = nxyz1 + ((size_t)bb*512 + j)*3;
    float dx = pp[0]-cc[0], dy = pp[1]-cc[1], dz = pp[2]-cc[2];
    const float* Fr = F + ((size_t)bb*512 + j)*128 + q*32;
    uint32_t hw[16], lw[16];
    #pragma unroll
    for (int u=0; u<32; u+=4){
        float4 f = *(const float4*)(Fr + u);
        int n = q*32 + u;
        float v0 = fmaxf(fmaf(sWx[(n+0)*3],dx, fmaf(sWx[(n+0)*3+1],dy, fmaf(sWx[(n+0)*3+2],dz, f.x + sB[n+0]))), 0.f);
        float v1 = fmaxf(fmaf(sWx[(n+1)*3],dx, fmaf(sWx[(n+1)*3+1],dy, fmaf(sWx[(n+1)*3+2],dz, f.y + sB[n+1]))), 0.f);
        float v2 = fmaxf(fmaf(sWx[(n+2)*3],dx, fmaf(sWx[(n+2)*3+1],dy, fmaf(sWx[(n+2)*3+2],dz, f.z + sB[n+2]))), 0.f);
        float v3 = fmaxf(fmaf(sWx[(n+3)*3],dx, fmaf(sWx[(n+3)*3+1],dy, fmaf(sWx[(n+3)*3+2],dz, f.w + sB[n+3]))), 0.f);
        __nv_bfloat16 h0,l0,h1,l1,h2,l2,h3,l3;
        splitbf(v0,h0,l0); splitbf(v1,h1,l1); splitbf(v2,h2,l2); splitbf(v3,h3,l3);
        hw[u>>1] = packbf(h0,h1); hw[(u>>1)+1] = packbf(h2,h3);
        lw[u>>1] = packbf(l0,l1); lw[(u>>1)+1] = packbf(l2,l3);
    }
    size_t o = (size_t)r*128 + q*32;
    #pragma unroll
    for (int p=0;p<4;p++){
        *(uint4*)(ohi + o + p*8) = make_uint4(hw[p*4],hw[p*4+1],hw[p*4+2],hw[p*4+3]);
        *(uint4*)(olo + o + p*8) = make_uint4(lw[p*4],lw[p*4+1],lw[p*4+2],lw[p*4+3]);
    }
}

// ---------------- build g3 (split bf16, K padded to 320) ----------------
__global__ void build_g3s_kernel(const float* __restrict__ nxyz2, const float* __restrict__ feat2,
                                 __nv_bfloat16* __restrict__ hi, __nv_bfloat16* __restrict__ lo){
    int e = blockIdx.x*blockDim.x + threadIdx.x;
    if (e >= 4096*320) return;
    int c = e % 320, r = e / 320;
    float v = (c<3) ? nxyz2[(size_t)r*3+c] : ((c<259) ? feat2[(size_t)r*256 + (c-3)] : 0.f);
    __nv_bfloat16 h, l; splitbf(v, h, l);
    hi[e] = h; lo[e] = l;
}

// ---------------- max pool over group dim ----------------
__global__ void maxpool_kernel(const float* __restrict__ in, float* __restrict__ out,
                               int G, int Kp, int C){
    int e = blockIdx.x*blockDim.x + threadIdx.x;
    if (e >= G*C) return;
    int g = e / C, c = e % C;
    const float* p = in + (size_t)g*Kp*C + c;
    float v = p[0];
    for (int k=1;k<Kp;k++) v = fmaxf(v, p[(size_t)k*C]);
    out[(size_t)g*C + c] = v;
}

// ---------------- bf16 mma.sync GEMM (3-pass hi/lo split, fp32-accurate) ----------------
// C[M,N] = relu?(A[M,K] @ W[N,K]^T + bias). A,W as bf16 hi/lo splits, K-major.
// M mult 128, K mult 32, N mult BN. Block 128xBN, BK=32, 256 thr, 8 warps 2(m)x4(n).
// Smem: b32 words, row stride 20 (conflict-free for both uint4 fill and fragment LDS).
// flags: bit0 relu, bit1 split-bf16 output (Chi/Clo) else fp32 (Cf).
template<int BN>
__global__ void __launch_bounds__(256, 1)
bmma_kernel(const __nv_bfloat16* __restrict__ Ahi, const __nv_bfloat16* __restrict__ Alo,
            const __nv_bfloat16* __restrict__ Whi, const __nv_bfloat16* __restrict__ Wlo,
            const float* __restrict__ bias,
            float* __restrict__ Cf, __nv_bfloat16* __restrict__ Chi, __nv_bfloat16* __restrict__ Clo,
            long long M, int N, int K, int flags)
{
    constexpr int NI  = BN/32;           // 8-col n-tiles per warp (4 or 2)
    constexpr int NB  = BN/64;           // B uint4 loads per thread per plane (2 or 1)
    constexpr int AW  = 20;              // smem word stride per row
    constexpr int APL = 128*AW;          // words per A plane
    constexpr int BPL = BN*AW;           // words per B plane
    __shared__ uint32_t Sa[2*APL];
    __shared__ uint32_t Sb[2*BPL];

    const int tid = threadIdx.x, lane = tid & 31, wid = tid >> 5;
    const int gID = lane >> 2, tig = lane & 3;
    const int wm = (wid & 1)*64;
    const int wn = (wid >> 1)*(8*NI);
    const long long bm = (long long)blockIdx.y * 128;
    const int bn = blockIdx.x * BN;

    float acc[4][NI][4];
    #pragma unroll
    for (int mi=0;mi<4;mi++)
        #pragma unroll
        for (int ni=0;ni<NI;ni++)
            #pragma unroll
            for (int r=0;r<4;r++) acc[mi][ni][r] = 0.f;

    const int lrow = tid >> 2;     // 0..63
    const int lq   = tid & 3;      // k-quad (8 bf16 = 16B each)

    uint4 rah[2], ral[2], rbh[NB], rbl[NB];
    auto ldg = [&](int k0){
        #pragma unroll
        for (int p=0;p<2;p++){
            long long gm = bm + lrow + p*64;
            rah[p] = *(const uint4*)(Ahi + gm*(long long)K + k0 + lq*8);
            ral[p] = *(const uint4*)(Alo + gm*(long long)K + k0 + lq*8);
        }
        #pragma unroll
        for (int p=0;p<NB;p++){
            int gn = bn + lrow + p*64;
            rbh[p] = *(const uint4*)(Whi + (size_t)gn*K + k0 + lq*8);
            rbl[p] = *(const uint4*)(Wlo + (size_t)gn*K + k0 + lq*8);
        }
    };
    auto sts = [&](){
        #pragma unroll
        for (int p=0;p<2;p++){
            int off = (lrow + p*64)*AW + lq*4;
            *(uint4*)(Sa + off)       = rah[p];
            *(uint4*)(Sa + APL + off) = ral[p];
        }
        #pragma unroll
        for (int p=0;p<NB;p++){
            int off = (lrow + p*64)*AW + lq*4;
            *(uint4*)(Sb + off)       = rbh[p];
            *(uint4*)(Sb + BPL + off) = rbl[p];
        }
    };

    const int T = K >> 5;
    ldg(0); sts(); __syncthreads();
    for (int t=0; t<T; t++){
        if (t+1 < T) ldg((t+1) << 5);
        #pragma unroll
        for (int h=0; h<2; h++){
            uint32_t ah[4][4], al[4][4];
            #pragma unroll
            for (int mi=0;mi<4;mi++){
                int r0 = (wm + mi*16 + gID)*AW + h*8 + tig;
                int r1 = r0 + 8*AW;
                ah[mi][0]=Sa[r0];   ah[mi][1]=Sa[r1];
                ah[mi][2]=Sa[r0+4]; ah[mi][3]=Sa[r1+4];
                al[mi][0]=Sa[APL+r0];   al[mi][1]=Sa[APL+r1];
                al[mi][2]=Sa[APL+r0+4]; al[mi][3]=Sa[APL+r1+4];
            }
            #pragma unroll
            for (int ni=0; ni<NI; ni++){
                int rb = (wn + ni*8 + gID)*AW + h*8 + tig;
                uint32_t bh0 = Sb[rb], bh1 = Sb[rb+4];
                uint32_t bl0 = Sb[BPL+rb], bl1 = Sb[BPL+rb+4];
                #pragma unroll
                for (int mi=0;mi<4;mi++){
                    MMA_BF16(acc[mi][ni], ah[mi][0],ah[mi][1],ah[mi][2],ah[mi][3], bh0,bh1);
                    MMA_BF16(acc[mi][ni], ah[mi][0],ah[mi][1],ah[mi][2],ah[mi][3], bl0,bl1);
                    MMA_BF16(acc[mi][ni], al[mi][0],al[mi][1],al[mi][2],al[mi][3], bh0,bh1);
                }
            }
        }
        __syncthreads();
        if (t+1 < T){ sts(); __syncthreads(); }
    }

    // epilogue: bias + optional relu; fp32 float2 stores or split bf16 b32 stores
    const bool relu  = (flags & 1) != 0;
    const bool split = (flags & 2) != 0;
    #pragma unroll
    for (int mi=0;mi<4;mi++){
        long long gm0 = bm + wm + mi*16 + gID;
        long long gm1 = gm0 + 8;
        #pragma unroll
        for (int ni=0;ni<NI;ni++){
            int gn = bn + wn + ni*8 + tig*2;
            float bv0 = bias[gn], bv1 = bias[gn+1];
            float v00 = acc[mi][ni][0] + bv0;
            float v01 = acc[mi][ni][1] + bv1;
            float v10 = acc[mi][ni][2] + bv0;
            float v11 = acc[mi][ni][3] + bv1;
            if (relu){
                v00 = fmaxf(v00,0.f); v01 = fmaxf(v01,0.f);
                v10 = fmaxf(v10,0.f); v11 = fmaxf(v11,0.f);
            }
            if (!split){
                *(float2*)(Cf + gm0*(long long)N + gn) = make_float2(v00, v01);
                *(float2*)(Cf + gm1*(long long)N + gn) = make_float2(v10, v11);
            } else {
                __nv_bfloat16 h0,l0,h1,l1;
                splitbf(v00,h0,l0); splitbf(v01,h1,l1);
                *(uint32_t*)(Chi + gm0*(long long)N + gn) = packbf(h0,h1);
                *(uint32_t*)(Clo + gm0*(long long)N + gn) = packbf(l0,l1);
                splitbf(v10,h0,l0); splitbf(v11,h1,l1);
                *(uint32_t*)(Chi + gm1*(long long)N + gn) = packbf(h0,h1);
                *(uint32_t*)(Clo + gm1*(long long)N + gn) = packbf(l0,l1);
            }
        }
    }
}

// ---------------- packed-f32x2 SGEMM (small GEMMs: F + FC head) ----------------
template<int BN>
__global__ void __launch_bounds__(256, 2)
f2gemm_kernel(const float* __restrict__ A, const float* __restrict__ Wt,
              const float* __restrict__ bias, float* __restrict__ C,
              long long M, int N, int K, int doRelu)
{
    constexpr int NP  = BN/16;
    constexpr int TNW = BN/8;
    constexpr int NB4 = (BN*16)/1024;
    __shared__ __align__(16) float As[128*20];
    __shared__ __align__(16) float Bs[16*BN];

    const int tid = threadIdx.x, lane = tid & 31, wid = tid >> 5;
    const int wm = (wid & 3)*32, wn = (wid >> 2)*(BN/2);
    const int tm = lane >> 2,  tn = lane & 3;
    const long long bm = (long long)blockIdx.y * 128;
    const int bn = blockIdx.x * BN;

    u64 acc[4][NP];
    #pragma unroll
    for (int i=0;i<4;i++)
        #pragma unroll
        for (int p=0;p<NP;p++) acc[i][p] = 0ull;

    uint4 ra[2], rb[NB4];
    auto ldg = [&](int k0){
        #pragma unroll
        for (int p=0;p<2;p++){
            int idx = tid + p*256;
            int m = idx >> 2, kq = idx & 3;
            long long gm = bm + m;
            ra[p] = (gm < M) ? *(const uint4*)(A + gm*(long long)K + k0 + kq*4)
                             : make_uint4(0,0,0,0);
        }
        #pragma unroll
        for (int p=0;p<NB4;p++){
            int idx = tid + p*256;
            int k = idx / (BN/4), nq = idx % (BN/4);
            int gn = bn + nq*4;
            rb[p] = (gn < N) ? *(const uint4*)(Wt + (size_t)(k0+k)*N + gn)
                             : make_uint4(0,0,0,0);
        }
    };
    auto sts = [&](){
        #pragma unroll
        for (int p=0;p<2;p++){
            int idx = tid + p*256;
            int m = idx >> 2, kq = idx & 3;
            *(uint4*)(As + m*20 + kq*4) = ra[p];
        }
        #pragma unroll
        for (int p=0;p<NB4;p++){
            int idx = tid + p*256;
            int k = idx / (BN/4), nq = idx % (BN/4);
            *(uint4*)(Bs + k*BN + nq*4) = rb[p];
        }
    };

    const int T = K / 16;
    ldg(0); sts(); __syncthreads();
    for (int t=0; t<T; t++){
        if (t+1 < T) ldg((t+1)*16);
        #pragma unroll
        for (int kk=0; kk<16; kk++){
            u64 a2[4];
            #pragma unroll
            for (int i=0;i<4;i++)
                a2[i] = pack2(As[(wm + tm + 8*i)*20 + kk]);
            u64 b2[NP];
            #pragma unroll
            for (int j=0;j<NP/2;j++){
                ulonglong2 v = *(const ulonglong2*)(Bs + kk*BN + wn + tn*TNW + j*4);
                b2[2*j]   = v.x;
                b2[2*j+1] = v.y;
            }
            #pragma unroll
            for (int i=0;i<4;i++)
                #pragma unroll
                for (int p=0;p<NP;p++)
                    fma2(acc[i][p], a2[i], b2[p]);
        }
        __syncthreads();
        if (t+1 < T){ sts(); __syncthreads(); }
    }

    const int n0 = bn + wn + tn*TNW;
    #pragma unroll
    for (int i=0;i<4;i++){
        long long gm = bm + wm + tm + 8*i;
        if (gm >= M) continue;
        #pragma unroll
        for (int j=0;j<NP/2;j++){
            int gn = n0 + j*4;
            if (gn >= N) continue;
            float4 bv = *(const float4*)(bias + gn);
            float2 p0 = unpack2(acc[i][2*j]);
            float2 p1 = unpack2(acc[i][2*j+1]);
            float4 o;
            o.x = p0.x + bv.x; o.y = p0.y + bv.y;
            o.z = p1.x + bv.z; o.w = p1.y + bv.w;
            if (doRelu){
                o.x = fmaxf(o.x,0.f); o.y = fmaxf(o.y,0.f);
                o.z = fmaxf(o.z,0.f); o.w = fmaxf(o.w,0.f);
            }
            *(float4*)(C + gm*(long long)N + gn) = o;
        }
    }
}

// ---------------- softmax over 40 classes, 32 rows ----------------
__global__ void softmax_kernel(const float* __restrict__ in, float* __restrict__ out){
    int b = threadIdx.y;
    int lane = threadIdx.x;
    float v0 = in[b*40 + lane];
    float v1 = (lane < 8) ? in[b*40 + lane + 32] : -INFINITY;
    float mx = fmaxf(v0, v1);
    #pragma unroll
    for (int off=16; off; off>>=1) mx = fmaxf(mx, __shfl_xor_sync(0xffffffffu, mx, off));
    float e0 = expf(v0 - mx);
    float e1 = (lane < 8) ? expf(v1 - mx) : 0.f;
    float sm = e0 + e1;
    #pragma unroll
    for (int off=16; off; off>>=1) sm += __shfl_xor_sync(0xffffffffu, sm, off);
    out[b*40 + lane] = e0 / sm;
    if (lane < 8) out[b*40 + lane + 32] = e1 / sm;
}

// ---------------- host side ----------------
static void bmma(const __nv_bfloat16* Ah, const __nv_bfloat16* Al,
                 const __nv_bfloat16* Wh, const __nv_bfloat16* Wl,
                 const float* bias, float* Cf, __nv_bfloat16* Ch, __nv_bfloat16* Cl,
                 long long M, int N, int K, int flags)
{
    if (N >= 128){
        dim3 g(N/128, (unsigned)(M/128));
        bmma_kernel<128><<<g, 256>>>(Ah,Al,Wh,Wl,bias,Cf,Ch,Cl,M,N,K,flags);
    } else {
        dim3 g(N/64, (unsigned)(M/128));
        bmma_kernel<64><<<g, 256>>>(Ah,Al,Wh,Wl,bias,Cf,Ch,Cl,M,N,K,flags);
    }
}

static void f2gemm(const float* A, const float* Wt, const float* bias, float* C,
                   long long M, int N, int K, int doRelu)
{
    int gy = (int)((M + 127)/128);
    if (N >= 128){
        dim3 grid(N/128, gy);
        f2gemm_kernel<128><<<grid, 256>>>(A, Wt, bias, C, M, N, K, doRelu);
    } else {
        dim3 grid((N+63)/64, gy);
        f2gemm_kernel<64><<<grid, 256>>>(A, Wt, bias, C, M, N, K, doRelu);
    }
}

static void transW(const float* W, float* Wt, int stride, int koff, int K, int Kpad, int N){
    int tot = Kpad*N;
    transpose_w_kernel<<<(tot+255)/256, 256>>>(W, Wt, stride, koff, K, Kpad, N);
}

static void splitW(const float* W, __nv_bfloat16* hi, __nv_bfloat16* lo, int Kin, int Kpad, int N){
    int tot = N*Kpad;
    split_w_kernel<<<(tot+255)/256, 256>>>(W, hi, lo, Kin, Kpad, N);
}

extern "C" void kernel_launch(void* const* d_in, const int* in_sizes, int n_in,
                              void* d_out, int out_size)
{
    (void)in_sizes; (void)n_in; (void)out_size;
    const float* x    = (const float*)d_in[0];
    const float* w1[3]= {(const float*)d_in[1],(const float*)d_in[3],(const float*)d_in[5]};
    const float* b1[3]= {(const float*)d_in[2],(const float*)d_in[4],(const float*)d_in[6]};
    const float* w2[3]= {(const float*)d_in[7],(const float*)d_in[9],(const float*)d_in[11]};
    const float* b2[3]= {(const float*)d_in[8],(const float*)d_in[10],(const float*)d_in[12]};
    const float* w3[3]= {(const float*)d_in[13],(const float*)d_in[15],(const float*)d_in[17]};
    const float* b3[3]= {(const float*)d_in[14],(const float*)d_in[16],(const float*)d_in[18]};
    const float* fc1w=(const float*)d_in[19]; const float* fc1b=(const float*)d_in[20];
    const float* fc2w=(const float*)d_in[21]; const float* fc2b=(const float*)d_in[22];
    const float* fc3w=(const float*)d_in[23]; const float* fc3b=(const float*)d_in[24];

    float4 *pts1, *pts2;
    int *fidx1, *fidx2, *idx1, *idx2;
    float *nxyz1, *nxyz2, *feat1, *feat2, *feat3, *fc1o, *fc2o, *logits, *zerob, *wts, *bufA, *bufB;
    __nv_bfloat16 *sAhi, *sAlo, *sBhi, *sBlo, *wbhi, *wblo;
    cudaGetSymbolAddress((void**)&pts1,  g_pts1);
    cudaGetSymbolAddress((void**)&pts2,  g_pts2);
    cudaGetSymbolAddress((void**)&fidx1, g_fidx1);
    cudaGetSymbolAddress((void**)&nxyz1, g_nxyz1);
    cudaGetSymbolAddress((void**)&idx1,  g_idx1);
    cudaGetSymbolAddress((void**)&fidx2, g_fidx2);
    cudaGetSymbolAddress((void**)&nxyz2, g_nxyz2);
    cudaGetSymbolAddress((void**)&idx2,  g_idx2);
    cudaGetSymbolAddress((void**)&feat1, g_feat1);
    cudaGetSymbolAddress((void**)&feat2, g_feat2);
    cudaGetSymbolAddress((void**)&feat3, g_feat3);
    cudaGetSymbolAddress((void**)&fc1o,  g_fc1o);
    cudaGetSymbolAddress((void**)&fc2o,  g_fc2o);
    cudaGetSymbolAddress((void**)&logits,g_logits);
    cudaGetSymbolAddress((void**)&zerob, g_zerob);
    cudaGetSymbolAddress((void**)&wts,   g_wts);
    cudaGetSymbolAddress((void**)&bufA,  g_bufA);
    cudaGetSymbolAddress((void**)&bufB,  g_bufB);
    cudaGetSymbolAddress((void**)&sAhi,  g_sAhi);
    cudaGetSymbolAddress((void**)&sAlo,  g_sAlo);
    cudaGetSymbolAddress((void**)&sBhi,  g_sBhi);
    cudaGetSymbolAddress((void**)&sBlo,  g_sBlo);
    cudaGetSymbolAddress((void**)&wbhi,  g_wbhi);
    cudaGetSymbolAddress((void**)&wblo,  g_wblo);

    // fp32 transposed weights (f2gemm path only)
    float* wt20f = wts + 0;        // K=128 N=128 (cols 3..130 of w2_0)
    float* fc1t  = wts + 16384;    // K=1024 N=512
    float* fc2t  = wts + 540672;   // K=512 N=256
    float* fc3t  = wts + 671744;   // K=256 N=40
    transW(w2[0], wt20f, 131, 3, 128, 128, 128);
    transW(fc1w,  fc1t, 1024, 0,1024,1024, 512);
    transW(fc2w,  fc2t,  512, 0, 512, 512, 256);
    transW(fc3w,  fc3t,  256, 0, 256, 256,  40);

    // bf16 split weights (mma path), [N, Kpad] K-major
    const int o11=0, o12=4096, o21=12288, o22=28672, o30=61440, o31=143360, o32=274432;
    splitW(w1[1], wbhi+o11, wblo+o11,  64,  64,   64);
    splitW(w1[2], wbhi+o12, wblo+o12,  64,  64,  128);
    splitW(w2[1], wbhi+o21, wblo+o21, 128, 128,  128);
    splitW(w2[2], wbhi+o22, wblo+o22, 128, 128,  256);
    splitW(w3[0], wbhi+o30, wblo+o30, 259, 320,  256);
    splitW(w3[1], wbhi+o31, wblo+o31, 256, 256,  512);
    splitW(w3[2], wbhi+o32, wblo+o32, 512, 512, 1024);

    // ---- SA1: npoint=512, r=0.2, K=32, MLP 3->64->64->128 ----
    prep_pts_kernel<<<(BB*NN+255)/256, 256>>>(x, pts1, BB*NN);
    fps_kernel<8><<<BB, 512>>>(x, NN, 512, fidx1, nxyz1);
    ball_kernel<32><<<(BB*512)/8, 256>>>(pts1, nxyz1, NN, 512, 0.04f, idx1);
    fused_g1l0s_kernel<<<524288/64, 256>>>(x, nxyz1, idx1, w1[0], b1[0], sAhi, sAlo);
    bmma(sAhi,sAlo, wbhi+o11,wblo+o11, b1[1], 0, sBhi,sBlo, 524288,  64,  64, 3);
    bmma(sBhi,sBlo, wbhi+o12,wblo+o12, b1[2], bufB, 0,0,    524288, 128,  64, 1);
    maxpool_kernel<<<(16384*128+255)/256, 256>>>(bufB, feat1, 16384, 32, 128);

    // ---- SA2: npoint=128, r=0.4, K=64, MLP 131->128->128->256 (layer1 factorized) ----
    prep_pts_kernel<<<(BB*512+255)/256, 256>>>(nxyz1, pts2, BB*512);
    fps_kernel<1><<<BB, 512>>>(nxyz1, 512, 128, fidx2, nxyz2);
    ball_kernel<64><<<(BB*128)/8, 256>>>(pts2, nxyz2, 512, 128, 0.16f, idx2);
    f2gemm(feat1, wt20f, zerob, bufA, 16384, 128, 128, 0);   // F = feat1 @ W0f^T
    fused_gather2s_kernel<<<262144/64, 256>>>(bufA, nxyz1, nxyz2, idx2, w2[0], b2[0], sAhi, sAlo);
    bmma(sAhi,sAlo, wbhi+o21,wblo+o21, b2[1], 0, sBhi,sBlo, 262144, 128, 128, 3);
    bmma(sBhi,sBlo, wbhi+o22,wblo+o22, b2[2], bufB, 0,0,    262144, 256, 128, 1);
    maxpool_kernel<<<(4096*256+255)/256, 256>>>(bufB, feat2, 4096, 64, 256);

    // ---- SA3 (group all): MLP 259->256->512->1024, max over 128 ----
    build_g3s_kernel<<<(4096*320+255)/256, 256>>>(nxyz2, feat2, sAhi, sAlo);
    bmma(sAhi,sAlo, wbhi+o30,wblo+o30, b3[0], 0, sBhi,sBlo, 4096,  256, 320, 3);
    bmma(sBhi,sBlo, wbhi+o31,wblo+o31, b3[1], 0, sAhi,sAlo, 4096,  512, 256, 3);
    bmma(sAhi,sAlo, wbhi+o32,wblo+o32, b3[2], bufB, 0,0,    4096, 1024, 512, 1);
    maxpool_kernel<<<(32*1024+255)/256, 256>>>(bufB, feat3, 32, 128, 1024);

    // ---- FC head + softmax ----
    f2gemm(feat3, fc1t, fc1b, fc1o,  32, 512, 1024, 1);
    f2gemm(fc1o,  fc2t, fc2b, fc2o,  32, 256,  512, 1);
    f2gemm(fc2o,  fc3t, fc3b, logits,32,  40,  256, 0);
    softmax_kernel<<<1, dim3(32,32)>>>(logits, (float*)d_out);
}